// round 13
// baseline (speedup 1.0000x reference)
#include <cuda_runtime.h>
#include <stdint.h>
#include <math.h>

// ---------------- sizes ----------------
// B=256, b3=768, D=1280, C=64, WIN=14, N=196, NH=8, HD=8, A=49
#define B3    768
#define NTOK  196
#define NHD   8
#define NAG   49

constexpr size_t SZ_XT    = 768ull * 12544;
constexpr size_t SZ_QKV   = 768ull * 196 * 192;
constexpr size_t SZ_T     = 768ull * 12544;
constexpr size_t SZ_OPROJ = 768ull * 12544;
constexpr size_t SZ_PB    = 8ull * 49 * 196;
constexpr size_t SZ_AB    = 8ull * 49 * 196;
constexpr size_t SZ_H     = 768ull * 256;
constexpr size_t SZ_SCR   = 28ull * 768 * 256;

constexpr size_t OFF_XT    = 0;
constexpr size_t OFF_QKV   = OFF_XT + SZ_XT;
constexpr size_t OFF_T     = OFF_QKV + SZ_QKV;
constexpr size_t OFF_OPROJ = OFF_T + SZ_T;
constexpr size_t OFF_PB    = OFF_OPROJ + SZ_OPROJ;
constexpr size_t OFF_AB    = OFF_PB + SZ_PB;
constexpr size_t OFF_H     = OFF_AB + SZ_AB;
constexpr size_t OFF_SCR   = OFF_H + SZ_H;
constexpr size_t WS_TOTAL  = OFF_SCR + SZ_SCR;

__device__ __align__(256) float g_ws[WS_TOTAL];

__device__ __forceinline__ uint32_t f2tf32(float x) {
    uint32_t u;
    asm("cvt.rna.tf32.f32 %0, %1;" : "=r"(u) : "f"(x));
    return u;
}

// ---------------- packed f32x2 helpers (sm_103a FFMA2) ----------------
typedef unsigned long long u64;
__device__ __forceinline__ u64 pk2(float lo, float hi) {
    u64 r; asm("mov.b64 %0, {%1,%2};" : "=l"(r) : "f"(lo), "f"(hi)); return r;
}
__device__ __forceinline__ void upk2(u64 v, float& lo, float& hi) {
    asm("mov.b64 {%0,%1}, %2;" : "=f"(lo), "=f"(hi) : "l"(v));
}
__device__ __forceinline__ u64 fma2(u64 a, u64 b, u64 c) {
    u64 d; asm("fma.rn.f32x2 %0, %1, %2, %3;" : "=l"(d) : "l"(a), "l"(b), "l"(c)); return d;
}
__device__ __forceinline__ u64 mul2(u64 a, u64 b) {
    u64 d; asm("mul.rn.f32x2 %0, %1, %2;" : "=l"(d) : "l"(a), "l"(b)); return d;
}
__device__ __forceinline__ u64 add2(u64 a, u64 b) {
    u64 d; asm("add.rn.f32x2 %0, %1, %2;" : "=l"(d) : "l"(a), "l"(b)); return d;
}

// ---------------- tf32 tensor-core NT GEMM, cp.async double-buffered ----------------
template<int BM, int BN, int WM, int WN>
__global__ void __launch_bounds__(256)
gemm_tf32(const float* __restrict__ A, const float* __restrict__ B,
          const float* __restrict__ bias, float* __restrict__ C,
          int M, int N, int K, int kChunk) {
    constexpr int BK = 32;
    constexpr int LD = 36;
    constexpr int WARPS_N = BN / WN;
    constexpr int MT = WM / 16;
    constexpr int NT = WN / 8;
    constexpr int A_IT = BM / 32;
    constexpr int B_IT = BN / 32;

    extern __shared__ float sm[];
    float* Asm = sm;
    float* Bsm = sm + 2 * BM * LD;

    const int tid = threadIdx.x;
    const int lane = tid & 31;
    const int warp = tid >> 5;
    const int wr = (warp / WARPS_N) * WM;
    const int wc = (warp % WARPS_N) * WN;
    const int gid = lane >> 2;
    const int tg  = lane & 3;

    const int kBase = blockIdx.z * kChunk;
    const float* Ab = A + (size_t)blockIdx.y * BM * K;
    const float* Bb = B + (size_t)blockIdx.x * BN * K;

    uint32_t aBase = (uint32_t)__cvta_generic_to_shared(Asm);
    uint32_t bBase = (uint32_t)__cvta_generic_to_shared(Bsm);

    auto issue = [&](int it) {
        int s = it & 1;
        int kt = kBase + it * BK;
#pragma unroll
        for (int t = 0; t < A_IT; t++) {
            int lin = tid + t * 256;
            int row = lin >> 3, cv = (lin & 7) << 2;
            const float* src = Ab + (size_t)row * K + kt + cv;
            uint32_t dst = aBase + (uint32_t)(((s * BM + row) * LD + cv) * 4);
            asm volatile("cp.async.cg.shared.global [%0], [%1], 16;\n" :: "r"(dst), "l"(src));
        }
#pragma unroll
        for (int t = 0; t < B_IT; t++) {
            int lin = tid + t * 256;
            int row = lin >> 3, cv = (lin & 7) << 2;
            const float* src = Bb + (size_t)row * K + kt + cv;
            uint32_t dst = bBase + (uint32_t)(((s * BN + row) * LD + cv) * 4);
            asm volatile("cp.async.cg.shared.global [%0], [%1], 16;\n" :: "r"(dst), "l"(src));
        }
        asm volatile("cp.async.commit_group;\n" ::: "memory");
    };

    float c[MT][NT][4];
#pragma unroll
    for (int i = 0; i < MT; i++)
#pragma unroll
        for (int j = 0; j < NT; j++)
#pragma unroll
            for (int r = 0; r < 4; r++) c[i][j][r] = 0.f;

    const int nIt = kChunk / BK;
    issue(0);

    for (int it = 0; it < nIt; it++) {
        asm volatile("cp.async.wait_group 0;\n" ::: "memory");
        __syncthreads();
        if (it + 1 < nIt) issue(it + 1);

        const int s = it & 1;
        const float* As_ = Asm + s * BM * LD;
        const float* Bs_ = Bsm + s * BN * LD;

#pragma unroll
        for (int kk = 0; kk < 4; kk++) {
            uint32_t af[MT][4];
            uint32_t bf[NT][2];
#pragma unroll
            for (int mt = 0; mt < MT; mt++) {
                int row = wr + mt * 16 + gid;
                af[mt][0] = f2tf32(As_[row * LD + kk * 8 + tg]);
                af[mt][1] = f2tf32(As_[(row + 8) * LD + kk * 8 + tg]);
                af[mt][2] = f2tf32(As_[row * LD + kk * 8 + tg + 4]);
                af[mt][3] = f2tf32(As_[(row + 8) * LD + kk * 8 + tg + 4]);
            }
#pragma unroll
            for (int nt = 0; nt < NT; nt++) {
                int col = wc + nt * 8 + gid;
                bf[nt][0] = f2tf32(Bs_[col * LD + kk * 8 + tg]);
                bf[nt][1] = f2tf32(Bs_[col * LD + kk * 8 + tg + 4]);
            }
#pragma unroll
            for (int mt = 0; mt < MT; mt++)
#pragma unroll
                for (int nt = 0; nt < NT; nt++) {
                    asm volatile(
                        "mma.sync.aligned.m16n8k8.row.col.f32.tf32.tf32.f32 "
                        "{%0,%1,%2,%3}, {%4,%5,%6,%7}, {%8,%9}, {%0,%1,%2,%3};\n"
                        : "+f"(c[mt][nt][0]), "+f"(c[mt][nt][1]),
                          "+f"(c[mt][nt][2]), "+f"(c[mt][nt][3])
                        : "r"(af[mt][0]), "r"(af[mt][1]), "r"(af[mt][2]), "r"(af[mt][3]),
                          "r"(bf[nt][0]), "r"(bf[nt][1]));
                }
        }
        __syncthreads();
    }

    const bool addb = (bias != nullptr) && (blockIdx.z == 0);
    float* Cz = C + (size_t)blockIdx.z * M * N;
#pragma unroll
    for (int mt = 0; mt < MT; mt++) {
        int row0 = blockIdx.y * BM + wr + mt * 16 + gid;
#pragma unroll
        for (int nt = 0; nt < NT; nt++) {
            int col = blockIdx.x * BN + wc + nt * 8 + tg * 2;
            float b0 = addb ? bias[col] : 0.f;
            float b1 = addb ? bias[col + 1] : 0.f;
            Cz[(size_t)row0 * N + col]           = c[mt][nt][0] + b0;
            Cz[(size_t)row0 * N + col + 1]       = c[mt][nt][1] + b1;
            Cz[(size_t)(row0 + 8) * N + col]     = c[mt][nt][2] + b0;
            Cz[(size_t)(row0 + 8) * N + col + 1] = c[mt][nt][3] + b1;
        }
    }
}

// ---------------- fp32 fallback GEMM (t2 only, tiny) ----------------
template<int BM, int BN, int TM, int TN>
__global__ void __launch_bounds__(256)
gemm_nt(const float* __restrict__ A, const float* __restrict__ B,
        const float* __restrict__ bias, float* __restrict__ C,
        int M, int N, int K, int kChunk) {
    constexpr int BK = 8;
    __shared__ float As[BK][BM];
    __shared__ float Bs[BK][BN];
    const int tid = threadIdx.x;
    const int kBase = blockIdx.z * kChunk;
    const float* Ab = A + (size_t)blockIdx.y * BM * K + kBase;
    const float* Bb = B + (size_t)blockIdx.x * BN * K + kBase;
    float acc[TM][TN];
#pragma unroll
    for (int i = 0; i < TM; i++)
#pragma unroll
        for (int j = 0; j < TN; j++) acc[i][j] = 0.f;

    const int tRow = (tid / (BN / TN)) * TM;
    const int tCol = (tid % (BN / TN)) * TN;

    for (int kt = 0; kt < kChunk; kt += BK) {
        for (int i = tid; i < BM * 2; i += 256) {
            int row = i >> 1, c4 = (i & 1) << 2;
            float4 v = *(const float4*)(Ab + (size_t)row * K + kt + c4);
            As[c4 + 0][row] = v.x; As[c4 + 1][row] = v.y;
            As[c4 + 2][row] = v.z; As[c4 + 3][row] = v.w;
        }
        for (int i = tid; i < BN * 2; i += 256) {
            int row = i >> 1, c4 = (i & 1) << 2;
            float4 v = *(const float4*)(Bb + (size_t)row * K + kt + c4);
            Bs[c4 + 0][row] = v.x; Bs[c4 + 1][row] = v.y;
            Bs[c4 + 2][row] = v.z; Bs[c4 + 3][row] = v.w;
        }
        __syncthreads();
#pragma unroll
        for (int k = 0; k < BK; k++) {
            float ra[TM], rb[TN];
#pragma unroll
            for (int i = 0; i < TM; i += 4)
                *(float4*)&ra[i] = *(const float4*)&As[k][tRow + i];
#pragma unroll
            for (int j = 0; j < TN; j += 4)
                *(float4*)&rb[j] = *(const float4*)&Bs[k][tCol + j];
#pragma unroll
            for (int i = 0; i < TM; i++)
#pragma unroll
                for (int j = 0; j < TN; j++)
                    acc[i][j] += ra[i] * rb[j];
        }
        __syncthreads();
    }

    float* Cb = C + (size_t)blockIdx.z * M * N
                  + (size_t)(blockIdx.y * BM + tRow) * N + blockIdx.x * BN + tCol;
    const bool addb = (bias != nullptr) && (blockIdx.z == 0);
#pragma unroll
    for (int i = 0; i < TM; i++)
#pragma unroll
        for (int j = 0; j < TN; j++) {
            float v = acc[i][j];
            if (addb) v += bias[blockIdx.x * BN + tCol + j];
            Cb[(size_t)i * N + j] = v;
        }
}

// ---------------- bilinear-resized position biases ----------------
// pb[h][a][n] (stage1); ab[h][a][n] (stage2, a-major for coalesced reads)
__global__ void bias_resize_kernel(const float* __restrict__ an, const float* __restrict__ na,
                                   const float* __restrict__ ah, const float* __restrict__ aw,
                                   const float* __restrict__ ha, const float* __restrict__ wa,
                                   float* __restrict__ pb, float* __restrict__ ab) {
    int i = blockIdx.x * 256 + threadIdx.x;
    if (i >= NHD * NAG * NTOK) return;
    int h = i / (NAG * NTOK);
    int rem = i % (NAG * NTOK);
    int a = rem / NTOK;
    int n = rem % NTOK;
    int r = n / 14, c = n % 14;

    auto coord = [](int j, int& i0, int& i1, float& w) {
        float src = (j + 0.5f) * 0.5f - 0.5f;
        src = fmaxf(src, 0.f);
        src = fminf(src, 6.f);
        i0 = (int)floorf(src);
        i1 = min(i0 + 1, 6);
        w = src - (float)i0;
    };
    int r0, r1, c0, c1; float wr, wc;
    coord(r, r0, r1, wr);
    coord(c, c0, c1, wc);

    const float* T1 = an + ((size_t)h * NAG + a) * 49;
    float v1 = (1.f - wr) * ((1.f - wc) * T1[r0 * 7 + c0] + wc * T1[r0 * 7 + c1])
             + wr * ((1.f - wc) * T1[r1 * 7 + c0] + wc * T1[r1 * 7 + c1]);
    pb[((size_t)h * NAG + a) * NTOK + n] =
        v1 + ah[((size_t)h * NAG + a) * 14 + r] + aw[((size_t)h * NAG + a) * 14 + c];

    const float* T2 = na + ((size_t)h * NAG + a) * 49;
    float v2 = (1.f - wr) * ((1.f - wc) * T2[r0 * 7 + c0] + wc * T2[r0 * 7 + c1])
             + wr * ((1.f - wc) * T2[r1 * 7 + c0] + wc * T2[r1 * 7 + c1]);
    ab[((size_t)h * NAG + a) * NTOK + n] =
        v2 + ha[((size_t)h * 14 + r) * NAG + a] + wa[((size_t)h * 14 + c) * NAG + a];
}

// ---------------- fused agent attention + depthwise conv ----------------
// Max-free softmax (scores bounded |s|<~1 by construction; exp cannot overflow;
// softmax without max subtraction is mathematically identical).
#define LDT 200
__global__ void __launch_bounds__(256)
attn_dwc_kernel(const float* __restrict__ qkv, const float* __restrict__ pb,
                const float* __restrict__ ab, const float* __restrict__ dwc_w,
                const float* __restrict__ dwc_b, float* __restrict__ t_out) {
    __shared__ float2 q2[4][LDT];
    __shared__ float2 k2[4][LDT];
    __shared__ float2 v2[4][LDT];
    __shared__ __align__(16) float2 ag2[NAG * 4];
    __shared__ __align__(16) float2 av2[NAG * 4];
    __shared__ float2 wsm2[9][4];
    __shared__ float2 bsm2[4];

    const int b = blockIdx.x >> 3, h = blockIdx.x & 7;
    const int tid = threadIdx.x;
    const float scale = 0.35355339059327373f;
    const float* base = qkv + (size_t)b * NTOK * 192 + h * 8;

    for (int i = tid; i < 392; i += 256) {
        int n = i >> 1, half = i & 1;
        int p = half << 1;
        const float* src = base + n * 192 + (half << 2);
        float4 q4 = *(const float4*)(src);
        float4 k4 = *(const float4*)(src + 64);
        float4 v4 = *(const float4*)(src + 128);
        q2[p + 0][n] = make_float2(q4.x, q4.y);
        q2[p + 1][n] = make_float2(q4.z, q4.w);
        k2[p + 0][n] = make_float2(k4.x, k4.y);
        k2[p + 1][n] = make_float2(k4.z, k4.w);
        v2[p + 0][n] = make_float2(v4.x, v4.y);
        v2[p + 1][n] = make_float2(v4.z, v4.w);
    }
    if (tid < 36) {
        int kk = tid >> 2, p = tid & 3;
        wsm2[kk][p] = make_float2(dwc_w[h * 72 + (2 * p) * 9 + kk],
                                  dwc_w[h * 72 + (2 * p + 1) * 9 + kk]);
    } else if (tid < 40) {
        int p = tid - 36;
        bsm2[p] = make_float2(dwc_b[h * 8 + 2 * p], dwc_b[h * 8 + 2 * p + 1]);
    }
    __syncthreads();

    const u64 QUART = pk2(0.25f, 0.25f);

    // agent tokens: 2x2 mean pool of q (packed)
    for (int i = tid; i < 196; i += 256) {
        int a = i >> 2, c = i & 3;
        int ar = a / 7, ac = a % 7;
        int n0 = ar * 28 + ac * 2;
        u64 s = add2(add2(*(const u64*)&q2[c][n0],     *(const u64*)&q2[c][n0 + 1]),
                     add2(*(const u64*)&q2[c][n0 + 14], *(const u64*)&q2[c][n0 + 15]));
        *(u64*)&ag2[a * 4 + c] = mul2(s, QUART);
    }
    __syncthreads();

    // ---- stage 1: 3 agent rows per pass, single fused pass (no max) ----
    const int warp = tid >> 5, lane = tid & 31;
    const float* pbh = pb + (size_t)h * NAG * NTOK;
    for (int c0 = 0; c0 < 7; c0 += 3) {
        const int a0 = warp + c0 * 8;
        const int a1 = warp + (c0 + 1) * 8;
        const int a2 = warp + (c0 + 2) * 8;
        const bool vv1 = (c0 + 1 < 7) && a1 < NAG;
        const bool vv2 = (c0 + 2 < 7) && a2 < NAG;
        if (a0 >= NAG) continue;

        u64 g0c[4], g1c[4], g2c[4];
#pragma unroll
        for (int c = 0; c < 4; c++) {
            g0c[c] = *(const u64*)&ag2[a0 * 4 + c];
            g1c[c] = vv1 ? *(const u64*)&ag2[a1 * 4 + c] : 0ull;
            g2c[c] = vv2 ? *(const u64*)&ag2[a2 * 4 + c] : 0ull;
        }

        float sum0 = 0.f, sum1 = 0.f, sum2 = 0.f;
        u64 A0[4], A1[4], A2[4];
#pragma unroll
        for (int c = 0; c < 4; c++) { A0[c] = 0; A1[c] = 0; A2[c] = 0; }

#pragma unroll
        for (int i = 0; i < 7; i++) {
            int n = lane + i * 32;
            bool nv = n < NTOK;
            int nn = nv ? n : 0;
            u64 kc[4];
#pragma unroll
            for (int c = 0; c < 4; c++) kc[c] = *(const u64*)&k2[c][nn];
            u64 vc[4];
#pragma unroll
            for (int c = 0; c < 4; c++) vc[c] = *(const u64*)&v2[c][nn];

            float lx, ly;
            u64 t0 = mul2(g0c[0], kc[0]);
            t0 = fma2(g0c[1], kc[1], t0);
            t0 = fma2(g0c[2], kc[2], t0);
            t0 = fma2(g0c[3], kc[3], t0);
            upk2(t0, lx, ly);
            float p0 = nv ? __expf((lx + ly) * scale + pbh[a0 * NTOK + nn]) : 0.f;
            sum0 += p0;
            u64 p02 = pk2(p0, p0);
#pragma unroll
            for (int c = 0; c < 4; c++) A0[c] = fma2(p02, vc[c], A0[c]);

            if (vv1) {
                u64 t1 = mul2(g1c[0], kc[0]);
                t1 = fma2(g1c[1], kc[1], t1);
                t1 = fma2(g1c[2], kc[2], t1);
                t1 = fma2(g1c[3], kc[3], t1);
                upk2(t1, lx, ly);
                float p1 = nv ? __expf((lx + ly) * scale + pbh[a1 * NTOK + nn]) : 0.f;
                sum1 += p1;
                u64 p12 = pk2(p1, p1);
#pragma unroll
                for (int c = 0; c < 4; c++) A1[c] = fma2(p12, vc[c], A1[c]);
            }
            if (vv2) {
                u64 t2 = mul2(g2c[0], kc[0]);
                t2 = fma2(g2c[1], kc[1], t2);
                t2 = fma2(g2c[2], kc[2], t2);
                t2 = fma2(g2c[3], kc[3], t2);
                upk2(t2, lx, ly);
                float p2 = nv ? __expf((lx + ly) * scale + pbh[a2 * NTOK + nn]) : 0.f;
                sum2 += p2;
                u64 p22 = pk2(p2, p2);
#pragma unroll
                for (int c = 0; c < 4; c++) A2[c] = fma2(p22, vc[c], A2[c]);
            }
        }
#pragma unroll
        for (int o = 16; o; o >>= 1) {
            sum0 += __shfl_xor_sync(0xffffffffu, sum0, o);
#pragma unroll
            for (int c = 0; c < 4; c++)
                A0[c] = add2(A0[c], __shfl_xor_sync(0xffffffffu, A0[c], o));
            if (vv1) {
                sum1 += __shfl_xor_sync(0xffffffffu, sum1, o);
#pragma unroll
                for (int c = 0; c < 4; c++)
                    A1[c] = add2(A1[c], __shfl_xor_sync(0xffffffffu, A1[c], o));
            }
            if (vv2) {
                sum2 += __shfl_xor_sync(0xffffffffu, sum2, o);
#pragma unroll
                for (int c = 0; c < 4; c++)
                    A2[c] = add2(A2[c], __shfl_xor_sync(0xffffffffu, A2[c], o));
            }
        }
        if (lane == 0) {
            float inv0 = 1.f / sum0;
#pragma unroll
            for (int c = 0; c < 4; c++) {
                float lx, ly; upk2(A0[c], lx, ly);
                av2[a0 * 4 + c] = make_float2(lx * inv0, ly * inv0);
            }
            if (vv1) {
                float inv1 = 1.f / sum1;
#pragma unroll
                for (int c = 0; c < 4; c++) {
                    float lx, ly; upk2(A1[c], lx, ly);
                    av2[a1 * 4 + c] = make_float2(lx * inv1, ly * inv1);
                }
            }
            if (vv2) {
                float inv2 = 1.f / sum2;
#pragma unroll
                for (int c = 0; c < 4; c++) {
                    float lx, ly; upk2(A2[c], lx, ly);
                    av2[a2 * 4 + c] = make_float2(lx * inv2, ly * inv2);
                }
            }
        }
    }
    __syncthreads();

    // ---- stage 2 + dwc: 2 tokens per thread (shared ag/av broadcasts), no max ----
    if (tid < 98) {
        const int n0 = 2 * tid, n1 = 2 * tid + 1;
        const float* abh = ab + (size_t)h * NAG * NTOK;   // [a][n]
        const u64 scale2 = pk2(scale, scale);
        u64 qa[4], qb[4];
#pragma unroll
        for (int c = 0; c < 4; c++) {
            qa[c] = mul2(*(const u64*)&q2[c][n0], scale2);
            qb[c] = mul2(*(const u64*)&q2[c][n1], scale2);
        }
        float sumA = 0.f, sumB = 0.f;
        u64 oa[4] = {0, 0, 0, 0}, ob[4] = {0, 0, 0, 0};
#pragma unroll 7
        for (int a = 0; a < NAG; a++) {
            u64 gc[4];
#pragma unroll
            for (int c = 0; c < 4; c++) gc[c] = *(const u64*)&ag2[a * 4 + c];
            float lx, ly;
            u64 tA = mul2(qa[0], gc[0]);
            tA = fma2(qa[1], gc[1], tA);
            tA = fma2(qa[2], gc[2], tA);
            tA = fma2(qa[3], gc[3], tA);
            upk2(tA, lx, ly);
            float pA = __expf(lx + ly + abh[a * NTOK + n0]);
            u64 tB = mul2(qb[0], gc[0]);
            tB = fma2(qb[1], gc[1], tB);
            tB = fma2(qb[2], gc[2], tB);
            tB = fma2(qb[3], gc[3], tB);
            upk2(tB, lx, ly);
            float pB = __expf(lx + ly + abh[a * NTOK + n1]);
            sumA += pA; sumB += pB;
            u64 pA2 = pk2(pA, pA), pB2 = pk2(pB, pB);
#pragma unroll
            for (int c = 0; c < 4; c++) {
                u64 w = *(const u64*)&av2[a * 4 + c];
                oa[c] = fma2(pA2, w, oa[c]);
                ob[c] = fma2(pB2, w, ob[c]);
            }
        }
        float invA = 1.f / sumA, invB = 1.f / sumB;
        u64 invA2 = pk2(invA, invA), invB2 = pk2(invB, invB);

        // depthwise 3x3 conv on v + residual, both tokens
#pragma unroll
        for (int t = 0; t < 2; t++) {
            const int n = t ? n1 : n0;
            const u64* oc = t ? ob : oa;
            const u64 inv2v = t ? invB2 : invA2;
            const int r = n / 14, col = n % 14;
            u64 resc[4];
#pragma unroll
            for (int c = 0; c < 4; c++)
                resc[c] = fma2(oc[c], inv2v, *(const u64*)&bsm2[c]);
#pragma unroll
            for (int dr = -1; dr <= 1; dr++) {
                int rr = r + dr;
                if (rr < 0 || rr > 13) continue;
#pragma unroll
                for (int dc = -1; dc <= 1; dc++) {
                    int cc = col + dc;
                    if (cc < 0 || cc > 13) continue;
                    int nn = rr * 14 + cc;
                    int kk = (dr + 1) * 3 + (dc + 1);
#pragma unroll
                    for (int c = 0; c < 4; c++)
                        resc[c] = fma2(*(const u64*)&wsm2[kk][c],
                                       *(const u64*)&v2[c][nn], resc[c]);
                }
            }
            float* tb = t_out + (size_t)b * 12544 + n * 64 + h * 8;
            float r0x, r0y, r1x, r1y;
            upk2(resc[0], r0x, r0y); upk2(resc[1], r1x, r1y);
            float4 w0 = {r0x, r0y, r1x, r1y};
            upk2(resc[2], r0x, r0y); upk2(resc[3], r1x, r1y);
            float4 w1 = {r0x, r0y, r1x, r1y};
            *(float4*)tb = w0;
            *(float4*)(tb + 4) = w1;
        }
    }
}

// ---------------- split-K reduces ----------------
__global__ void reduce_adj(const float* __restrict__ part, float* __restrict__ out) {
    int i = blockIdx.x * 256 + threadIdx.x;
    if (i >= 768 * 256) return;
    float s = 0.f;
#pragma unroll
    for (int z = 0; z < 28; z++) s += part[(size_t)z * 768 * 256 + i];
    out[i] = s;
}

__global__ void reduce_tanh(const float* __restrict__ part, float* __restrict__ hbuf) {
    int i = blockIdx.x * 256 + threadIdx.x;
    if (i >= 768 * 256) return;
    float s = 0.f;
#pragma unroll
    for (int z = 0; z < 8; z++) s += part[(size_t)z * 768 * 256 + i];
    hbuf[i] = tanhf(s);
}

__global__ void reduce_t2(const float* __restrict__ part, float* __restrict__ dout) {
    int i = blockIdx.x * 256 + threadIdx.x;
    if (i >= 768 * 128) return;
    float s = 0.f;
#pragma unroll
    for (int z = 0; z < 4; z++) s += part[(size_t)z * 768 * 128 + i];
    int r = i >> 7, j = i & 127;
    int b = r / 3, which = r % 3;
    dout[(size_t)which * 32768 + b * 128 + j] = s;
}

// ---------------- launch ----------------
extern "C" void kernel_launch(void* const* d_in, const int* in_sizes, int n_in,
                              void* d_out, int out_size) {
    (void)in_sizes; (void)n_in; (void)out_size;
    const float* X       = (const float*)d_in[0];
    const float* W_embed = (const float*)d_in[1];
    const float* b_embed = (const float*)d_in[2];
    const float* W_qkv   = (const float*)d_in[3];
    const float* W_proj  = (const float*)d_in[4];
    const float* b_proj  = (const float*)d_in[5];
    const float* dwc_w   = (const float*)d_in[6];
    const float* dwc_b   = (const float*)d_in[7];
    const float* an_bias = (const float*)d_in[8];
    const float* na_bias = (const float*)d_in[9];
    const float* ah_bias = (const float*)d_in[10];
    const float* aw_bias = (const float*)d_in[11];
    const float* ha_bias = (const float*)d_in[12];
    const float* wa_bias = (const float*)d_in[13];
    const float* W_adj   = (const float*)d_in[14];
    const float* b_adj   = (const float*)d_in[15];
    const float* W_t1    = (const float*)d_in[16];
    const float* b_t1    = (const float*)d_in[17];
    const float* W_t2    = (const float*)d_in[18];
    const float* b_t2    = (const float*)d_in[19];
    float* out = (float*)d_out;

    float* ws = nullptr;
    cudaGetSymbolAddress((void**)&ws, g_ws);
    float* xt    = ws + OFF_XT;
    float* qkv   = ws + OFF_QKV;
    float* tbuf  = ws + OFF_T;
    float* oproj = ws + OFF_OPROJ;
    float* pb    = ws + OFF_PB;
    float* ab    = ws + OFF_AB;
    float* hbuf  = ws + OFF_H;
    float* scr   = ws + OFF_SCR;

    const int SMEM_W256 = 2 * (128 * 36 + 256 * 36) * 4;  // 110592 B
    const int SMEM_128  = 2 * (128 * 36 + 128 * 36) * 4;  // 73728 B
    const int SMEM_64   = 2 * (128 * 36 + 64 * 36) * 4;   // 55296 B
    cudaFuncSetAttribute(gemm_tf32<128, 256, 64, 64>,
                         cudaFuncAttributeMaxDynamicSharedMemorySize, SMEM_W256);
    cudaFuncSetAttribute(gemm_tf32<128, 128, 64, 32>,
                         cudaFuncAttributeMaxDynamicSharedMemorySize, SMEM_128);
    cudaFuncSetAttribute(gemm_tf32<128, 64, 32, 32>,
                         cudaFuncAttributeMaxDynamicSharedMemorySize, SMEM_64);

    bias_resize_kernel<<<(NHD * NAG * NTOK + 255) / 256, 256>>>(
        an_bias, na_bias, ah_bias, aw_bias, ha_bias, wa_bias, pb, ab);

    // embed: (768,1280) x (12544,1280)^T + b -> xt
    gemm_tf32<128, 256, 64, 64><<<dim3(49, 6, 1), 256, SMEM_W256>>>(
        X, W_embed, b_embed, xt, 768, 12544, 1280, 1280);

    // qkv: (150528,64) x (192,64)^T -> qkv
    gemm_tf32<128, 64, 32, 32><<<dim3(3, 1176, 1), 256, SMEM_64>>>(
        xt, W_qkv, nullptr, qkv, 150528, 192, 64, 64);

    // fused agent attention + dwc -> tbuf
    attn_dwc_kernel<<<B3 * NHD, 256>>>(qkv, pb, ab, dwc_w, dwc_b, tbuf);

    // proj: (150528,64) x (64,64)^T + b -> oproj
    gemm_tf32<128, 64, 32, 32><<<dim3(1, 1176, 1), 256, SMEM_64>>>(
        tbuf, W_proj, b_proj, oproj, 150528, 64, 64, 64);

    // adj: (768,12544) x (256,12544)^T + b, BN=256, split 28
    gemm_tf32<128, 256, 64, 64><<<dim3(1, 6, 28), 256, SMEM_W256>>>(
        oproj, W_adj, b_adj, scr, 768, 256, 12544, 448);
    reduce_adj<<<768, 256>>>(scr, out + 98304);

    // MLP t1: (768,1280) x (256,1280)^T + b, split 8, tanh -> hbuf
    gemm_tf32<128, 128, 64, 32><<<dim3(2, 6, 8), 256, SMEM_128>>>(
        X, W_t1, b_t1, scr, 768, 256, 1280, 160);
    reduce_tanh<<<768, 256>>>(scr, hbuf);

    // MLP t2: (768,256) x (128,256)^T + b, split 4 -> anchor/pos/neg
    gemm_nt<128, 64, 8, 4><<<dim3(2, 6, 4), 256>>>(
        hbuf, W_t2, b_t2, scr, 768, 128, 256, 64);
    reduce_t2<<<(768 * 128 + 255) / 256, 256>>>(scr, out);
}

// round 16
// speedup vs baseline: 1.2525x; 1.2525x over previous
#include <cuda_runtime.h>
#include <stdint.h>
#include <math.h>

// ---------------- sizes ----------------
// B=256, b3=768, D=1280, C=64, WIN=14, N=196, NH=8, HD=8, A=49
#define B3    768
#define NTOK  196
#define NHD   8
#define NAG   49

constexpr size_t SZ_XT    = 768ull * 12544;
constexpr size_t SZ_QKV   = 768ull * 196 * 192;
constexpr size_t SZ_T     = 768ull * 12544;
constexpr size_t SZ_OPROJ = 768ull * 12544;
constexpr size_t SZ_PB    = 8ull * 49 * 196;
constexpr size_t SZ_AB    = 8ull * 49 * 196;
constexpr size_t SZ_H     = 768ull * 256;
constexpr size_t SZ_SCR   = 28ull * 768 * 256;

constexpr size_t OFF_XT    = 0;
constexpr size_t OFF_QKV   = OFF_XT + SZ_XT;
constexpr size_t OFF_T     = OFF_QKV + SZ_QKV;
constexpr size_t OFF_OPROJ = OFF_T + SZ_T;
constexpr size_t OFF_PB    = OFF_OPROJ + SZ_OPROJ;
constexpr size_t OFF_AB    = OFF_PB + SZ_PB;
constexpr size_t OFF_H     = OFF_AB + SZ_AB;
constexpr size_t OFF_SCR   = OFF_H + SZ_H;
constexpr size_t WS_TOTAL  = OFF_SCR + SZ_SCR;

__device__ __align__(256) float g_ws[WS_TOTAL];

__device__ __forceinline__ uint32_t f2tf32(float x) {
    uint32_t u;
    asm("cvt.rna.tf32.f32 %0, %1;" : "=r"(u) : "f"(x));
    return u;
}

// ---------------- packed f32x2 helpers (sm_103a FFMA2) ----------------
typedef unsigned long long u64;
__device__ __forceinline__ u64 pk2(float lo, float hi) {
    u64 r; asm("mov.b64 %0, {%1,%2};" : "=l"(r) : "f"(lo), "f"(hi)); return r;
}
__device__ __forceinline__ void upk2(u64 v, float& lo, float& hi) {
    asm("mov.b64 {%0,%1}, %2;" : "=f"(lo), "=f"(hi) : "l"(v));
}
__device__ __forceinline__ u64 fma2(u64 a, u64 b, u64 c) {
    u64 d; asm("fma.rn.f32x2 %0, %1, %2, %3;" : "=l"(d) : "l"(a), "l"(b), "l"(c)); return d;
}
__device__ __forceinline__ u64 mul2(u64 a, u64 b) {
    u64 d; asm("mul.rn.f32x2 %0, %1, %2;" : "=l"(d) : "l"(a), "l"(b)); return d;
}
__device__ __forceinline__ u64 add2(u64 a, u64 b) {
    u64 d; asm("add.rn.f32x2 %0, %1, %2;" : "=l"(d) : "l"(a), "l"(b)); return d;
}

// ---------------- tf32 tensor-core NT GEMM, cp.async double-buffered ----------------
template<int BM, int BN, int WM, int WN>
__global__ void __launch_bounds__(256)
gemm_tf32(const float* __restrict__ A, const float* __restrict__ B,
          const float* __restrict__ bias, float* __restrict__ C,
          int M, int N, int K, int kChunk) {
    constexpr int BK = 32;
    constexpr int LD = 36;
    constexpr int WARPS_N = BN / WN;
    constexpr int MT = WM / 16;
    constexpr int NT = WN / 8;
    constexpr int A_IT = BM / 32;
    constexpr int B_IT = BN / 32;

    extern __shared__ float sm[];
    float* Asm = sm;
    float* Bsm = sm + 2 * BM * LD;

    const int tid = threadIdx.x;
    const int lane = tid & 31;
    const int warp = tid >> 5;
    const int wr = (warp / WARPS_N) * WM;
    const int wc = (warp % WARPS_N) * WN;
    const int gid = lane >> 2;
    const int tg  = lane & 3;

    const int kBase = blockIdx.z * kChunk;
    const float* Ab = A + (size_t)blockIdx.y * BM * K;
    const float* Bb = B + (size_t)blockIdx.x * BN * K;

    uint32_t aBase = (uint32_t)__cvta_generic_to_shared(Asm);
    uint32_t bBase = (uint32_t)__cvta_generic_to_shared(Bsm);

    auto issue = [&](int it) {
        int s = it & 1;
        int kt = kBase + it * BK;
#pragma unroll
        for (int t = 0; t < A_IT; t++) {
            int lin = tid + t * 256;
            int row = lin >> 3, cv = (lin & 7) << 2;
            const float* src = Ab + (size_t)row * K + kt + cv;
            uint32_t dst = aBase + (uint32_t)(((s * BM + row) * LD + cv) * 4);
            asm volatile("cp.async.cg.shared.global [%0], [%1], 16;\n" :: "r"(dst), "l"(src));
        }
#pragma unroll
        for (int t = 0; t < B_IT; t++) {
            int lin = tid + t * 256;
            int row = lin >> 3, cv = (lin & 7) << 2;
            const float* src = Bb + (size_t)row * K + kt + cv;
            uint32_t dst = bBase + (uint32_t)(((s * BN + row) * LD + cv) * 4);
            asm volatile("cp.async.cg.shared.global [%0], [%1], 16;\n" :: "r"(dst), "l"(src));
        }
        asm volatile("cp.async.commit_group;\n" ::: "memory");
    };

    float c[MT][NT][4];
#pragma unroll
    for (int i = 0; i < MT; i++)
#pragma unroll
        for (int j = 0; j < NT; j++)
#pragma unroll
            for (int r = 0; r < 4; r++) c[i][j][r] = 0.f;

    const int nIt = kChunk / BK;
    issue(0);

    for (int it = 0; it < nIt; it++) {
        asm volatile("cp.async.wait_group 0;\n" ::: "memory");
        __syncthreads();
        if (it + 1 < nIt) issue(it + 1);

        const int s = it & 1;
        const float* As_ = Asm + s * BM * LD;
        const float* Bs_ = Bsm + s * BN * LD;

#pragma unroll
        for (int kk = 0; kk < 4; kk++) {
            uint32_t af[MT][4];
            uint32_t bf[NT][2];
#pragma unroll
            for (int mt = 0; mt < MT; mt++) {
                int row = wr + mt * 16 + gid;
                af[mt][0] = f2tf32(As_[row * LD + kk * 8 + tg]);
                af[mt][1] = f2tf32(As_[(row + 8) * LD + kk * 8 + tg]);
                af[mt][2] = f2tf32(As_[row * LD + kk * 8 + tg + 4]);
                af[mt][3] = f2tf32(As_[(row + 8) * LD + kk * 8 + tg + 4]);
            }
#pragma unroll
            for (int nt = 0; nt < NT; nt++) {
                int col = wc + nt * 8 + gid;
                bf[nt][0] = f2tf32(Bs_[col * LD + kk * 8 + tg]);
                bf[nt][1] = f2tf32(Bs_[col * LD + kk * 8 + tg + 4]);
            }
#pragma unroll
            for (int mt = 0; mt < MT; mt++)
#pragma unroll
                for (int nt = 0; nt < NT; nt++) {
                    asm volatile(
                        "mma.sync.aligned.m16n8k8.row.col.f32.tf32.tf32.f32 "
                        "{%0,%1,%2,%3}, {%4,%5,%6,%7}, {%8,%9}, {%0,%1,%2,%3};\n"
                        : "+f"(c[mt][nt][0]), "+f"(c[mt][nt][1]),
                          "+f"(c[mt][nt][2]), "+f"(c[mt][nt][3])
                        : "r"(af[mt][0]), "r"(af[mt][1]), "r"(af[mt][2]), "r"(af[mt][3]),
                          "r"(bf[nt][0]), "r"(bf[nt][1]));
                }
        }
        __syncthreads();
    }

    const bool addb = (bias != nullptr) && (blockIdx.z == 0);
    float* Cz = C + (size_t)blockIdx.z * M * N;
#pragma unroll
    for (int mt = 0; mt < MT; mt++) {
        int row0 = blockIdx.y * BM + wr + mt * 16 + gid;
#pragma unroll
        for (int nt = 0; nt < NT; nt++) {
            int col = blockIdx.x * BN + wc + nt * 8 + tg * 2;
            float b0 = addb ? bias[col] : 0.f;
            float b1 = addb ? bias[col + 1] : 0.f;
            Cz[(size_t)row0 * N + col]           = c[mt][nt][0] + b0;
            Cz[(size_t)row0 * N + col + 1]       = c[mt][nt][1] + b1;
            Cz[(size_t)(row0 + 8) * N + col]     = c[mt][nt][2] + b0;
            Cz[(size_t)(row0 + 8) * N + col + 1] = c[mt][nt][3] + b1;
        }
    }
}

// ---------------- fp32 fallback GEMM (t2 only, tiny) ----------------
template<int BM, int BN, int TM, int TN>
__global__ void __launch_bounds__(256)
gemm_nt(const float* __restrict__ A, const float* __restrict__ B,
        const float* __restrict__ bias, float* __restrict__ C,
        int M, int N, int K, int kChunk) {
    constexpr int BK = 8;
    __shared__ float As[BK][BM];
    __shared__ float Bs[BK][BN];
    const int tid = threadIdx.x;
    const int kBase = blockIdx.z * kChunk;
    const float* Ab = A + (size_t)blockIdx.y * BM * K + kBase;
    const float* Bb = B + (size_t)blockIdx.x * BN * K + kBase;
    float acc[TM][TN];
#pragma unroll
    for (int i = 0; i < TM; i++)
#pragma unroll
        for (int j = 0; j < TN; j++) acc[i][j] = 0.f;

    const int tRow = (tid / (BN / TN)) * TM;
    const int tCol = (tid % (BN / TN)) * TN;

    for (int kt = 0; kt < kChunk; kt += BK) {
        for (int i = tid; i < BM * 2; i += 256) {
            int row = i >> 1, c4 = (i & 1) << 2;
            float4 v = *(const float4*)(Ab + (size_t)row * K + kt + c4);
            As[c4 + 0][row] = v.x; As[c4 + 1][row] = v.y;
            As[c4 + 2][row] = v.z; As[c4 + 3][row] = v.w;
        }
        for (int i = tid; i < BN * 2; i += 256) {
            int row = i >> 1, c4 = (i & 1) << 2;
            float4 v = *(const float4*)(Bb + (size_t)row * K + kt + c4);
            Bs[c4 + 0][row] = v.x; Bs[c4 + 1][row] = v.y;
            Bs[c4 + 2][row] = v.z; Bs[c4 + 3][row] = v.w;
        }
        __syncthreads();
#pragma unroll
        for (int k = 0; k < BK; k++) {
            float ra[TM], rb[TN];
#pragma unroll
            for (int i = 0; i < TM; i += 4)
                *(float4*)&ra[i] = *(const float4*)&As[k][tRow + i];
#pragma unroll
            for (int j = 0; j < TN; j += 4)
                *(float4*)&rb[j] = *(const float4*)&Bs[k][tCol + j];
#pragma unroll
            for (int i = 0; i < TM; i++)
#pragma unroll
                for (int j = 0; j < TN; j++)
                    acc[i][j] += ra[i] * rb[j];
        }
        __syncthreads();
    }

    float* Cb = C + (size_t)blockIdx.z * M * N
                  + (size_t)(blockIdx.y * BM + tRow) * N + blockIdx.x * BN + tCol;
    const bool addb = (bias != nullptr) && (blockIdx.z == 0);
#pragma unroll
    for (int i = 0; i < TM; i++)
#pragma unroll
        for (int j = 0; j < TN; j++) {
            float v = acc[i][j];
            if (addb) v += bias[blockIdx.x * BN + tCol + j];
            Cb[(size_t)i * N + j] = v;
        }
}

// ---------------- bilinear-resized position biases ----------------
// pb[h][a][n] (stage1); ab[h][a][n] (stage2, a-major for coalesced reads)
__global__ void bias_resize_kernel(const float* __restrict__ an, const float* __restrict__ na,
                                   const float* __restrict__ ah, const float* __restrict__ aw,
                                   const float* __restrict__ ha, const float* __restrict__ wa,
                                   float* __restrict__ pb, float* __restrict__ ab) {
    int i = blockIdx.x * 256 + threadIdx.x;
    if (i >= NHD * NAG * NTOK) return;
    int h = i / (NAG * NTOK);
    int rem = i % (NAG * NTOK);
    int a = rem / NTOK;
    int n = rem % NTOK;
    int r = n / 14, c = n % 14;

    auto coord = [](int j, int& i0, int& i1, float& w) {
        float src = (j + 0.5f) * 0.5f - 0.5f;
        src = fmaxf(src, 0.f);
        src = fminf(src, 6.f);
        i0 = (int)floorf(src);
        i1 = min(i0 + 1, 6);
        w = src - (float)i0;
    };
    int r0, r1, c0, c1; float wr, wc;
    coord(r, r0, r1, wr);
    coord(c, c0, c1, wc);

    const float* T1 = an + ((size_t)h * NAG + a) * 49;
    float v1 = (1.f - wr) * ((1.f - wc) * T1[r0 * 7 + c0] + wc * T1[r0 * 7 + c1])
             + wr * ((1.f - wc) * T1[r1 * 7 + c0] + wc * T1[r1 * 7 + c1]);
    pb[((size_t)h * NAG + a) * NTOK + n] =
        v1 + ah[((size_t)h * NAG + a) * 14 + r] + aw[((size_t)h * NAG + a) * 14 + c];

    const float* T2 = na + ((size_t)h * NAG + a) * 49;
    float v2 = (1.f - wr) * ((1.f - wc) * T2[r0 * 7 + c0] + wc * T2[r0 * 7 + c1])
             + wr * ((1.f - wc) * T2[r1 * 7 + c0] + wc * T2[r1 * 7 + c1]);
    ab[((size_t)h * NAG + a) * NTOK + n] =
        v2 + ha[((size_t)h * 14 + r) * NAG + a] + wa[((size_t)h * 14 + c) * NAG + a];
}

// ---------------- fused agent attention + depthwise conv (packed f32x2) ----------------
// Max-free softmax: scores are bounded (|s| ~ 1) so exp cannot overflow and
// softmax without max subtraction is mathematically identical.
#define LDT 200
__global__ void __launch_bounds__(256)
attn_dwc_kernel(const float* __restrict__ qkv, const float* __restrict__ pb,
                const float* __restrict__ ab, const float* __restrict__ dwc_w,
                const float* __restrict__ dwc_b, float* __restrict__ t_out) {
    // d-dim packed into 4 float2 carriers
    __shared__ float2 q2[4][LDT];
    __shared__ float2 k2[4][LDT];
    __shared__ float2 v2[4][LDT];
    __shared__ __align__(16) float2 ag2[NAG * 4];
    __shared__ __align__(16) float2 av2[NAG * 4];
    __shared__ float2 wsm2[9][4];
    __shared__ float2 bsm2[4];

    const int b = blockIdx.x >> 3, h = blockIdx.x & 7;
    const int tid = threadIdx.x;
    const float scale = 0.35355339059327373f;
    const float* base = qkv + (size_t)b * NTOK * 192 + h * 8;

    for (int i = tid; i < 392; i += 256) {
        int n = i >> 1, half = i & 1;
        int p = half << 1;                    // carrier pair index 0 or 2
        const float* src = base + n * 192 + (half << 2);
        float4 q4 = *(const float4*)(src);
        float4 k4 = *(const float4*)(src + 64);
        float4 v4 = *(const float4*)(src + 128);
        q2[p + 0][n] = make_float2(q4.x, q4.y);
        q2[p + 1][n] = make_float2(q4.z, q4.w);
        k2[p + 0][n] = make_float2(k4.x, k4.y);
        k2[p + 1][n] = make_float2(k4.z, k4.w);
        v2[p + 0][n] = make_float2(v4.x, v4.y);
        v2[p + 1][n] = make_float2(v4.z, v4.w);
    }
    if (tid < 36) {
        int kk = tid >> 2, p = tid & 3;
        wsm2[kk][p] = make_float2(dwc_w[h * 72 + (2 * p) * 9 + kk],
                                  dwc_w[h * 72 + (2 * p + 1) * 9 + kk]);
    } else if (tid < 40) {
        int p = tid - 36;
        bsm2[p] = make_float2(dwc_b[h * 8 + 2 * p], dwc_b[h * 8 + 2 * p + 1]);
    }
    __syncthreads();

    const u64 QUART = pk2(0.25f, 0.25f);

    // agent tokens: 2x2 mean pool of q (packed)
    for (int i = tid; i < 196; i += 256) {
        int a = i >> 2, c = i & 3;
        int ar = a / 7, ac = a % 7;
        int n0 = ar * 28 + ac * 2;
        u64 s = add2(add2(*(const u64*)&q2[c][n0],     *(const u64*)&q2[c][n0 + 1]),
                     add2(*(const u64*)&q2[c][n0 + 14], *(const u64*)&q2[c][n0 + 15]));
        *(u64*)&ag2[a * 4 + c] = mul2(s, QUART);
    }
    __syncthreads();

    // ---- stage 1: 3 agent rows per pass; two-loop (regs bounded); no max ----
    const int warp = tid >> 5, lane = tid & 31;
    const float* pbh = pb + (size_t)h * NAG * NTOK;
    for (int c0 = 0; c0 < 7; c0 += 3) {
        const int a0 = warp + c0 * 8;
        const int a1 = warp + (c0 + 1) * 8;
        const int a2 = warp + (c0 + 2) * 8;
        const bool vv1 = (c0 + 1 < 7) && a1 < NAG;
        const bool vv2 = (c0 + 2 < 7) && a2 < NAG;
        if (a0 >= NAG) continue;

        u64 g0c[4], g1c[4], g2c[4];
#pragma unroll
        for (int c = 0; c < 4; c++) {
            g0c[c] = *(const u64*)&ag2[a0 * 4 + c];
            g1c[c] = vv1 ? *(const u64*)&ag2[a1 * 4 + c] : 0ull;
            g2c[c] = vv2 ? *(const u64*)&ag2[a2 * 4 + c] : 0ull;
        }

        // loop 1: raw scores into e[] (exp-ready; -1e30 sentinel -> exp=0)
        float e0[7], e1[7], e2[7];
#pragma unroll
        for (int i = 0; i < 7; i++) {
            int n = lane + i * 32;
            bool nv = n < NTOK;
            int nn = nv ? n : 0;
            u64 kc[4];
#pragma unroll
            for (int c = 0; c < 4; c++) kc[c] = *(const u64*)&k2[c][nn];
            float s0 = -1e30f, s1 = -1e30f, s2 = -1e30f;
            if (nv) {
                float lx, ly;
                u64 t0 = mul2(g0c[0], kc[0]);
                t0 = fma2(g0c[1], kc[1], t0);
                t0 = fma2(g0c[2], kc[2], t0);
                t0 = fma2(g0c[3], kc[3], t0);
                upk2(t0, lx, ly);
                s0 = (lx + ly) * scale + pbh[a0 * NTOK + n];
                if (vv1) {
                    u64 t1 = mul2(g1c[0], kc[0]);
                    t1 = fma2(g1c[1], kc[1], t1);
                    t1 = fma2(g1c[2], kc[2], t1);
                    t1 = fma2(g1c[3], kc[3], t1);
                    upk2(t1, lx, ly);
                    s1 = (lx + ly) * scale + pbh[a1 * NTOK + n];
                }
                if (vv2) {
                    u64 t2 = mul2(g2c[0], kc[0]);
                    t2 = fma2(g2c[1], kc[1], t2);
                    t2 = fma2(g2c[2], kc[2], t2);
                    t2 = fma2(g2c[3], kc[3], t2);
                    upk2(t2, lx, ly);
                    s2 = (lx + ly) * scale + pbh[a2 * NTOK + n];
                }
            }
            e0[i] = s0; e1[i] = s1; e2[i] = s2;
        }

        // loop 2: exp + accumulate (no max subtraction)
        float sum0 = 0.f, sum1 = 0.f, sum2 = 0.f;
        u64 A0[4], A1[4], A2[4];
#pragma unroll
        for (int c = 0; c < 4; c++) { A0[c] = 0; A1[c] = 0; A2[c] = 0; }
#pragma unroll
        for (int i = 0; i < 7; i++) {
            int n = lane + i * 32;
            bool nv = n < NTOK;
            int nn = nv ? n : 0;
            u64 vc[4];
#pragma unroll
            for (int c = 0; c < 4; c++) vc[c] = nv ? *(const u64*)&v2[c][nn] : 0ull;
            float p0 = __expf(e0[i]);           // e=-1e30 -> 0
            sum0 += p0;
            u64 p02 = pk2(p0, p0);
#pragma unroll
            for (int c = 0; c < 4; c++) A0[c] = fma2(p02, vc[c], A0[c]);
            if (vv1) {
                float p1 = __expf(e1[i]);
                sum1 += p1;
                u64 p12 = pk2(p1, p1);
#pragma unroll
                for (int c = 0; c < 4; c++) A1[c] = fma2(p12, vc[c], A1[c]);
            }
            if (vv2) {
                float p2 = __expf(e2[i]);
                sum2 += p2;
                u64 p22 = pk2(p2, p2);
#pragma unroll
                for (int c = 0; c < 4; c++) A2[c] = fma2(p22, vc[c], A2[c]);
            }
        }
#pragma unroll
        for (int o = 16; o; o >>= 1) {
            sum0 += __shfl_xor_sync(0xffffffffu, sum0, o);
#pragma unroll
            for (int c = 0; c < 4; c++)
                A0[c] = add2(A0[c], __shfl_xor_sync(0xffffffffu, A0[c], o));
            if (vv1) {
                sum1 += __shfl_xor_sync(0xffffffffu, sum1, o);
#pragma unroll
                for (int c = 0; c < 4; c++)
                    A1[c] = add2(A1[c], __shfl_xor_sync(0xffffffffu, A1[c], o));
            }
            if (vv2) {
                sum2 += __shfl_xor_sync(0xffffffffu, sum2, o);
#pragma unroll
                for (int c = 0; c < 4; c++)
                    A2[c] = add2(A2[c], __shfl_xor_sync(0xffffffffu, A2[c], o));
            }
        }
        if (lane == 0) {
            float inv0 = 1.f / sum0;
#pragma unroll
            for (int c = 0; c < 4; c++) {
                float lx, ly; upk2(A0[c], lx, ly);
                av2[a0 * 4 + c] = make_float2(lx * inv0, ly * inv0);
            }
            if (vv1) {
                float inv1 = 1.f / sum1;
#pragma unroll
                for (int c = 0; c < 4; c++) {
                    float lx, ly; upk2(A1[c], lx, ly);
                    av2[a1 * 4 + c] = make_float2(lx * inv1, ly * inv1);
                }
            }
            if (vv2) {
                float inv2 = 1.f / sum2;
#pragma unroll
                for (int c = 0; c < 4; c++) {
                    float lx, ly; upk2(A2[c], lx, ly);
                    av2[a2 * 4 + c] = make_float2(lx * inv2, ly * inv2);
                }
            }
        }
    }
    __syncthreads();

    // ---- stage 2 + dwc: thread per token, max-free softmax, packed ----
    if (tid < NTOK) {
        const int n = tid;
        const float* abh = ab + (size_t)h * NAG * NTOK;   // [a][n]
        const u64 scale2 = pk2(scale, scale);
        u64 qc[4];
#pragma unroll
        for (int c = 0; c < 4; c++) qc[c] = mul2(*(const u64*)&q2[c][n], scale2);
        float sum = 0.f;
        u64 oc[4] = {0, 0, 0, 0};
#pragma unroll 7
        for (int a = 0; a < NAG; a++) {
            u64 t = mul2(qc[0], *(const u64*)&ag2[a * 4 + 0]);
            t = fma2(qc[1], *(const u64*)&ag2[a * 4 + 1], t);
            t = fma2(qc[2], *(const u64*)&ag2[a * 4 + 2], t);
            t = fma2(qc[3], *(const u64*)&ag2[a * 4 + 3], t);
            float lx, ly; upk2(t, lx, ly);
            float p = __expf(lx + ly + abh[a * NTOK + n]);
            sum += p;
            u64 p2p = pk2(p, p);
#pragma unroll
            for (int c = 0; c < 4; c++)
                oc[c] = fma2(p2p, *(const u64*)&av2[a * 4 + c], oc[c]);
        }
        float inv = 1.f / sum;
        u64 inv2 = pk2(inv, inv);

        // depthwise 3x3 conv on v + residual (packed)
        const int r = n / 14, col = n % 14;
        u64 resc[4];
#pragma unroll
        for (int c = 0; c < 4; c++)
            resc[c] = fma2(oc[c], inv2, *(const u64*)&bsm2[c]);
#pragma unroll
        for (int dr = -1; dr <= 1; dr++) {
            int rr = r + dr;
            if (rr < 0 || rr > 13) continue;
#pragma unroll
            for (int dc = -1; dc <= 1; dc++) {
                int cc = col + dc;
                if (cc < 0 || cc > 13) continue;
                int nn = rr * 14 + cc;
                int kk = (dr + 1) * 3 + (dc + 1);
#pragma unroll
                for (int c = 0; c < 4; c++)
                    resc[c] = fma2(*(const u64*)&wsm2[kk][c],
                                   *(const u64*)&v2[c][nn], resc[c]);
            }
        }
        float* tb = t_out + (size_t)b * 12544 + n * 64 + h * 8;
        float r0x, r0y, r1x, r1y;
        upk2(resc[0], r0x, r0y); upk2(resc[1], r1x, r1y);
        float4 w0 = {r0x, r0y, r1x, r1y};
        upk2(resc[2], r0x, r0y); upk2(resc[3], r1x, r1y);
        float4 w1 = {r0x, r0y, r1x, r1y};
        *(float4*)tb = w0;
        *(float4*)(tb + 4) = w1;
    }
}

// ---------------- split-K reduces ----------------
__global__ void reduce_adj(const float* __restrict__ part, float* __restrict__ out) {
    int i = blockIdx.x * 256 + threadIdx.x;
    if (i >= 768 * 256) return;
    float s = 0.f;
#pragma unroll
    for (int z = 0; z < 28; z++) s += part[(size_t)z * 768 * 256 + i];
    out[i] = s;
}

__global__ void reduce_tanh(const float* __restrict__ part, float* __restrict__ hbuf) {
    int i = blockIdx.x * 256 + threadIdx.x;
    if (i >= 768 * 256) return;
    float s = 0.f;
#pragma unroll
    for (int z = 0; z < 8; z++) s += part[(size_t)z * 768 * 256 + i];
    hbuf[i] = tanhf(s);
}

__global__ void reduce_t2(const float* __restrict__ part, float* __restrict__ dout) {
    int i = blockIdx.x * 256 + threadIdx.x;
    if (i >= 768 * 128) return;
    float s = 0.f;
#pragma unroll
    for (int z = 0; z < 4; z++) s += part[(size_t)z * 768 * 128 + i];
    int r = i >> 7, j = i & 127;
    int b = r / 3, which = r % 3;
    dout[(size_t)which * 32768 + b * 128 + j] = s;
}

// ---------------- launch ----------------
extern "C" void kernel_launch(void* const* d_in, const int* in_sizes, int n_in,
                              void* d_out, int out_size) {
    (void)in_sizes; (void)n_in; (void)out_size;
    const float* X       = (const float*)d_in[0];
    const float* W_embed = (const float*)d_in[1];
    const float* b_embed = (const float*)d_in[2];
    const float* W_qkv   = (const float*)d_in[3];
    const float* W_proj  = (const float*)d_in[4];
    const float* b_proj  = (const float*)d_in[5];
    const float* dwc_w   = (const float*)d_in[6];
    const float* dwc_b   = (const float*)d_in[7];
    const float* an_bias = (const float*)d_in[8];
    const float* na_bias = (const float*)d_in[9];
    const float* ah_bias = (const float*)d_in[10];
    const float* aw_bias = (const float*)d_in[11];
    const float* ha_bias = (const float*)d_in[12];
    const float* wa_bias = (const float*)d_in[13];
    const float* W_adj   = (const float*)d_in[14];
    const float* b_adj   = (const float*)d_in[15];
    const float* W_t1    = (const float*)d_in[16];
    const float* b_t1    = (const float*)d_in[17];
    const float* W_t2    = (const float*)d_in[18];
    const float* b_t2    = (const float*)d_in[19];
    float* out = (float*)d_out;

    float* ws = nullptr;
    cudaGetSymbolAddress((void**)&ws, g_ws);
    float* xt    = ws + OFF_XT;
    float* qkv   = ws + OFF_QKV;
    float* tbuf  = ws + OFF_T;
    float* oproj = ws + OFF_OPROJ;
    float* pb    = ws + OFF_PB;
    float* ab    = ws + OFF_AB;
    float* hbuf  = ws + OFF_H;
    float* scr   = ws + OFF_SCR;

    const int SMEM_W256 = 2 * (128 * 36 + 256 * 36) * 4;  // 110592 B
    const int SMEM_128  = 2 * (128 * 36 + 128 * 36) * 4;  // 73728 B
    const int SMEM_64   = 2 * (128 * 36 + 64 * 36) * 4;   // 55296 B
    cudaFuncSetAttribute(gemm_tf32<128, 256, 64, 64>,
                         cudaFuncAttributeMaxDynamicSharedMemorySize, SMEM_W256);
    cudaFuncSetAttribute(gemm_tf32<128, 128, 64, 32>,
                         cudaFuncAttributeMaxDynamicSharedMemorySize, SMEM_128);
    cudaFuncSetAttribute(gemm_tf32<128, 64, 32, 32>,
                         cudaFuncAttributeMaxDynamicSharedMemorySize, SMEM_64);

    bias_resize_kernel<<<(NHD * NAG * NTOK + 255) / 256, 256>>>(
        an_bias, na_bias, ah_bias, aw_bias, ha_bias, wa_bias, pb, ab);

    // embed: (768,1280) x (12544,1280)^T + b -> xt
    gemm_tf32<128, 256, 64, 64><<<dim3(49, 6, 1), 256, SMEM_W256>>>(
        X, W_embed, b_embed, xt, 768, 12544, 1280, 1280);

    // qkv: (150528,64) x (192,64)^T -> qkv
    gemm_tf32<128, 64, 32, 32><<<dim3(3, 1176, 1), 256, SMEM_64>>>(
        xt, W_qkv, nullptr, qkv, 150528, 192, 64, 64);

    // fused agent attention + dwc -> tbuf
    attn_dwc_kernel<<<B3 * NHD, 256>>>(qkv, pb, ab, dwc_w, dwc_b, tbuf);

    // proj: (150528,64) x (64,64)^T + b -> oproj
    gemm_tf32<128, 64, 32, 32><<<dim3(1, 1176, 1), 256, SMEM_64>>>(
        tbuf, W_proj, b_proj, oproj, 150528, 64, 64, 64);

    // adj: (768,12544) x (256,12544)^T + b, BN=256, split 28
    gemm_tf32<128, 256, 64, 64><<<dim3(1, 6, 28), 256, SMEM_W256>>>(
        oproj, W_adj, b_adj, scr, 768, 256, 12544, 448);
    reduce_adj<<<768, 256>>>(scr, out + 98304);

    // MLP t1: (768,1280) x (256,1280)^T + b, split 8, tanh -> hbuf
    gemm_tf32<128, 128, 64, 32><<<dim3(2, 6, 8), 256, SMEM_128>>>(
        X, W_t1, b_t1, scr, 768, 256, 1280, 160);
    reduce_tanh<<<768, 256>>>(scr, hbuf);

    // MLP t2: (768,256) x (128,256)^T + b, split 4 -> anchor/pos/neg
    gemm_nt<128, 64, 8, 4><<<dim3(2, 6, 4), 256>>>(
        hbuf, W_t2, b_t2, scr, 768, 128, 256, 64);
    reduce_t2<<<(768 * 128 + 255) / 256, 256>>>(scr, out);
}